// round 1
// baseline (speedup 1.0000x reference)
#include <cuda_runtime.h>
#include <math.h>

#define Bmax 1024
#define Nn   100
#define Hh   128
#define NHEADS 8
#define HD   16
#define NPAD 101
#define JALL 384
#define NEGV -1000000000.0f

// ---- device scratch (no cudaMalloc allowed) ----
__device__ float g_Wcat[Hh * JALL];            // [k][j] combined Wk^T | Wv^T | Wk2^T@Wo
__device__ float g_Wqf [Hh * (Hh + 1)];        // Wq @ fc_w   (128 x 129)
__device__ float g_Wq1 [Hh * Hh];              // Wq @ fc1_w  (128 x 128)
__device__ float g_qpool[Bmax * Hh];           // (pool @ fc1_w^T) @ Wq^T
__device__ float g_EncProj[(size_t)Bmax * JALL * Nn];  // [b][j][n]

// =====================================================================
// Kernel 1: combine small weight matrices
// blocks 0..383  : column j of Wcat
// blocks 384..511: row i of Wqf = Wq @ fc_w
// blocks 512..639: row i of Wq1 = Wq @ fc1_w
// =====================================================================
__global__ void weights_kernel(const float* __restrict__ fc_w,
                               const float* __restrict__ fc1_w,
                               const float* __restrict__ Wq,
                               const float* __restrict__ Wk,
                               const float* __restrict__ Wv,
                               const float* __restrict__ Wo,
                               const float* __restrict__ Wk2)
{
    int bid = blockIdx.x, t = threadIdx.x;   // t = 0..127
    if (bid < 384) {
        int j = bid;
        float v;
        if (j < 128) {
            v = Wk[j * 128 + t];
        } else if (j < 256) {
            v = Wv[(j - 128) * 128 + t];
        } else {
            int jp = j - 256;
            float s = 0.f;
            for (int h = 0; h < 128; h++) s += Wk2[h * 128 + t] * Wo[h * 128 + jp];
            v = s;
        }
        g_Wcat[t * 384 + j] = v;
    } else if (bid < 512) {
        int i = bid - 384;
        for (int k = t; k < 129; k += 128) {
            float s = 0.f;
            for (int j = 0; j < 128; j++) s += Wq[i * 128 + j] * fc_w[j * 129 + k];
            g_Wqf[i * 129 + k] = s;
        }
    } else {
        int i = bid - 512;
        float s = 0.f;
        for (int j = 0; j < 128; j++) s += Wq[i * 128 + j] * fc1_w[j * 128 + t];
        g_Wq1[i * 128 + t] = s;
    }
}

// =====================================================================
// Kernel 2: qpool[b][h] = sum_k Wq1[h][k] * pool[b][k]
// =====================================================================
__global__ void qpool_kernel(const float* __restrict__ pool)
{
    int b = blockIdx.x, h = threadIdx.x;
    float s = 0.f;
    for (int k = 0; k < 128; k++) s += g_Wq1[h * 128 + k] * pool[b * 128 + k];
    g_qpool[b * 128 + h] = s;
}

// =====================================================================
// Kernel 3: EncProj[b][j][n] = sum_k enc[b][n][k] * Wcat[k][j]
// one block per batch, 384 threads, weight column in registers.
// =====================================================================
__global__ __launch_bounds__(384, 1)
void encproj_kernel(const float* __restrict__ enc)
{
    extern __shared__ float As[];            // [100][128] row-major
    int b = blockIdx.x, t = threadIdx.x;
    for (int i = t; i < Nn * Hh; i += 384) As[i] = enc[(size_t)b * Nn * Hh + i];
    float w[128];
#pragma unroll
    for (int k = 0; k < 128; k++) w[k] = g_Wcat[k * 384 + t];
    __syncthreads();

    float* op = g_EncProj + (size_t)b * JALL * Nn + (size_t)t * Nn;
    for (int n0 = 0; n0 < Nn; n0 += 4) {
        float a0 = 0.f, a1 = 0.f, a2 = 0.f, a3 = 0.f;
        const float4* r0 = reinterpret_cast<const float4*>(&As[(n0 + 0) * Hh]);
        const float4* r1 = reinterpret_cast<const float4*>(&As[(n0 + 1) * Hh]);
        const float4* r2 = reinterpret_cast<const float4*>(&As[(n0 + 2) * Hh]);
        const float4* r3 = reinterpret_cast<const float4*>(&As[(n0 + 3) * Hh]);
#pragma unroll
        for (int kk = 0; kk < 32; kk++) {
            float4 x0 = r0[kk];
            a0 += x0.x * w[4*kk] + x0.y * w[4*kk+1] + x0.z * w[4*kk+2] + x0.w * w[4*kk+3];
            float4 x1 = r1[kk];
            a1 += x1.x * w[4*kk] + x1.y * w[4*kk+1] + x1.z * w[4*kk+2] + x1.w * w[4*kk+3];
            float4 x2 = r2[kk];
            a2 += x2.x * w[4*kk] + x2.y * w[4*kk+1] + x2.z * w[4*kk+2] + x2.w * w[4*kk+3];
            float4 x3 = r3[kk];
            a3 += x3.x * w[4*kk] + x3.y * w[4*kk+1] + x3.z * w[4*kk+2] + x3.w * w[4*kk+3];
        }
        reinterpret_cast<float4*>(op + n0)[0] = make_float4(a0, a1, a2, a3);
    }
}

// =====================================================================
// Kernel 4: persistent per-batch decoder. One block = one batch,
// all n_steps inside. All operand matrices in shared memory.
// =====================================================================
#define DEC_SMEM_FLOATS 57300
#define DEC_SMEM_BYTES  (DEC_SMEM_FLOATS * 4)

__global__ __launch_bounds__(256, 1)
void decode_kernel(const float* __restrict__ enc,
                   const float* __restrict__ capacity,
                   const float* __restrict__ demand,
                   const int*   __restrict__ Tptr,
                   float* __restrict__ out, int ns, int B)
{
    extern __shared__ float sm[];
    float* KT    = sm;                    // 128*101  K transposed [h'][n]
    float* VT    = KT   + Hh * NPAD;      // 128*101
    float* K2T   = VT   + Hh * NPAD;      // 128*101  (K2 @ Wo) transposed
    float* Wqf   = K2T  + Hh * NPAD;      // 128*129
    float* qp    = Wqf  + Hh * 129;       // 128
    float* x     = qp   + 128;            // 132 (129 used: [inp, cap])
    float* q     = x    + 132;            // 128
    float* att   = q    + 128;            // 800 (8 heads x 100)
    float* g     = att  + 800;            // 128
    float* u     = g    + 128;            // 104
    float* mask  = u    + 104;            // 104
    float* mask1 = mask + 104;            // 104
    float* dem   = mask1+ 104;            // 104
    float* red   = dem  + 104;            // 256
    float* misc  = red  + 256;            // 16: [0]=cap [1]=base [2]=logp [3]=invT
    int*   imisc = (int*)(misc + 8);      // [0]=idx  [1]=visited

    int b = blockIdx.x, t = threadIdx.x;
    const int w = t >> 5, lane = t & 31;

    // ---- load per-batch operands into smem (transposed, pad 101) ----
    const float* ep = g_EncProj + (size_t)b * JALL * Nn;
    for (int i = t; i < JALL * Nn; i += 256) {
        int j = i / Nn, n = i - j * Nn;
        sm[(j >> 7) * (Hh * NPAD) + (j & 127) * NPAD + n] = ep[i];
    }
    for (int i = t; i < Hh * 129; i += 256) Wqf[i] = g_Wqf[i];
    if (t < 128) qp[t] = g_qpool[b * 128 + t];
    if (t < Nn) { dem[t] = demand[b * Nn + t]; mask1[t] = 0.f; }
    if (t < 128) x[t] = enc[(size_t)b * Nn * Hh + t];     // node 0 row
    if (t == 0) {
        float c = capacity[b];
        misc[0] = c;                 // cap
        misc[1] = capacity[0];       // base_cap
        misc[2] = 0.f;               // logp accumulator
        misc[3] = 1.0f / (float)(*Tptr);
        x[128] = c;
        imisc[0] = 0; imisc[1] = 0;
    }
    __syncthreads();

    // ---- initial update_mask (index = 0, mask1 = 0) ----
    {
        float capc = misc[0];
        int pred = 1;
        if (t >= 1 && t < Nn) {
            float m = (dem[t] > capc) ? 1.f : 0.f;
            mask[t] = m; pred = (m > 0.f);
        }
        int allc = __syncthreads_and(pred);
        if (t == 0) mask[0] = allc ? 0.f : 1.f;
        __syncthreads();
    }

    for (int step = 0; step < ns; step++) {
        // ---- q = [inp,cap] @ Wqf^T + qpool  (2 threads per output) ----
        {
            int h = t & 127, part = t >> 7;
            int k0 = part * 65, k1 = part ? 129 : 65;
            const float* wr = Wqf + h * 129;
            float s = 0.f;
            for (int k = k0; k < k1; k++) s += wr[k] * x[k];
            red[t] = s;
        }
        __syncthreads();
        if (t < 128) q[t] = qp[t] + red[t] + red[t + 128];
        __syncthreads();

        // ---- scores (masked) ----
        for (int idx = t; idx < NHEADS * Nn; idx += 256) {
            int head = idx / Nn, n = idx - head * Nn;
            const float* kp = KT + head * HD * NPAD + n;
            const float* qh = q + head * HD;
            float s = 0.f;
#pragma unroll
            for (int d = 0; d < HD; d++) s += qh[d] * kp[d * NPAD];
            s *= 0.25f;                       // 1/sqrt(16)
            if (mask[n] > 0.f) s = NEGV;
            att[idx] = s;
        }
        __syncthreads();

        // ---- softmax per head (warp w handles head w) ----
        {
            float v0 = att[w * Nn + lane];
            float v1 = att[w * Nn + lane + 32];
            float v2 = att[w * Nn + lane + 64];
            float v3 = (lane < 4) ? att[w * Nn + lane + 96] : -3.4e38f;
            float m = fmaxf(fmaxf(v0, v1), fmaxf(v2, v3));
#pragma unroll
            for (int off = 16; off; off >>= 1) m = fmaxf(m, __shfl_xor_sync(0xffffffffu, m, off));
            float e0 = expf(v0 - m), e1 = expf(v1 - m), e2 = expf(v2 - m);
            float e3 = (lane < 4) ? expf(v3 - m) : 0.f;
            float ssum = e0 + e1 + e2 + e3;
#pragma unroll
            for (int off = 16; off; off >>= 1) ssum += __shfl_xor_sync(0xffffffffu, ssum, off);
            float inv = 1.f / ssum;
            att[w * Nn + lane]      = e0 * inv;
            att[w * Nn + lane + 32] = e1 * inv;
            att[w * Nn + lane + 64] = e2 * inv;
            if (lane < 4) att[w * Nn + lane + 96] = e3 * inv;
        }
        __syncthreads();

        // ---- g = attn @ V ----
        if (t < 128) {
            const float* vp = VT + t * NPAD;
            const float* ap = att + (t >> 4) * Nn;
            float s = 0.f;
            for (int n = 0; n < Nn; n++) s += ap[n] * vp[n];
            g[t] = s;
        }
        __syncthreads();

        // ---- u = CLIP * tanh(g . K2W / sqrt(H)), masked ----
        if (t < Nn) {
            const float* kp = K2T + t;
            float s = 0.f;
            for (int j = 0; j < Hh; j++) s += g[j] * kp[j * NPAD];
            float uu = 10.f * tanhf(s * 0.088388347648318447f);  // 1/sqrt(128)
            if (mask[t] > 0.f) uu = NEGV;
            u[t] = uu;
        }
        __syncthreads();

        // ---- argmax + log-softmax + state update (warp 0) ----
        if (w == 0) {
            float invT = misc[3];
            float v0 = u[lane] * invT;
            float v1 = u[lane + 32] * invT;
            float v2 = u[lane + 64] * invT;
            float v3 = (lane < 4) ? u[lane + 96] * invT : -3.4e38f;
            float best = v0; int bi = lane;
            if (v1 > best) { best = v1; bi = lane + 32; }
            if (v2 > best) { best = v2; bi = lane + 64; }
            if (v3 > best) { best = v3; bi = lane + 96; }
#pragma unroll
            for (int off = 16; off; off >>= 1) {
                float ov = __shfl_xor_sync(0xffffffffu, best, off);
                int   oi = __shfl_xor_sync(0xffffffffu, bi,   off);
                if (ov > best || (ov == best && oi < bi)) { best = ov; bi = oi; }
            }
            float m = best;   // max == value at argmax
            float e0 = expf(v0 - m), e1 = expf(v1 - m), e2 = expf(v2 - m);
            float e3 = (lane < 4) ? expf(v3 - m) : 0.f;
            float ssum = e0 + e1 + e2 + e3;
#pragma unroll
            for (int off = 16; off; off >>= 1) ssum += __shfl_xor_sync(0xffffffffu, ssum, off);
            if (lane == 0) {
                int idx = bi;
                imisc[0] = idx;
                // is_done uses mask1 BEFORE this step's update
                if (imisc[1] < Nn - 1) misc[2] += -logf(ssum);
                out[(size_t)b * ns + step] = (float)idx;
                float c = (idx == 0) ? misc[1] : misc[0] - dem[idx];
                misc[0] = c;
                x[128] = c;
                if (idx > 0 && mask1[idx] == 0.f) { mask1[idx] = 1.f; imisc[1] += 1; }
            }
        }
        __syncthreads();

        // ---- gather next input row + update_mask ----
        int sidx = imisc[0];
        float capc = misc[0];
        if (t < 128) x[t] = enc[(size_t)b * Nn * Hh + (size_t)sidx * Hh + t];
        int pred = 1;
        if (t >= 1 && t < Nn) {
            float m = (mask1[t] > 0.f || dem[t] > capc) ? 1.f : 0.f;
            mask[t] = m; pred = (m > 0.f);
        }
        int allc = __syncthreads_and(pred);
        if (t == 0) mask[0] = allc ? 0.f : (sidx == 0 ? 1.f : 0.f);
        __syncthreads();
    }

    if (t == 0) out[(size_t)B * ns + b] = misc[2];
}

// =====================================================================
// launch
// =====================================================================
extern "C" void kernel_launch(void* const* d_in, const int* in_sizes, int n_in,
                              void* d_out, int out_size)
{
    const float* enc      = (const float*)d_in[0];
    const float* pool     = (const float*)d_in[1];
    const float* capacity = (const float*)d_in[2];
    const float* demand   = (const float*)d_in[3];
    const float* fc_w     = (const float*)d_in[4];
    const float* fc1_w    = (const float*)d_in[5];
    const float* Wq       = (const float*)d_in[6];
    const float* Wk       = (const float*)d_in[7];
    const float* Wv       = (const float*)d_in[8];
    const float* Wo       = (const float*)d_in[9];
    const float* Wk2      = (const float*)d_in[10];
    const int*   Tptr     = (const int*)d_in[12];

    int B  = in_sizes[0] / (Nn * Hh);          // 1024
    int ns = out_size / B - 1;                 // 128 (actions) ; +1 row of log_p
    float* out = (float*)d_out;

    weights_kernel<<<640, 128>>>(fc_w, fc1_w, Wq, Wk, Wv, Wo, Wk2);
    qpool_kernel<<<B, 128>>>(pool);

    cudaFuncSetAttribute(encproj_kernel, cudaFuncAttributeMaxDynamicSharedMemorySize, Nn * Hh * 4);
    encproj_kernel<<<B, 384, Nn * Hh * 4>>>(enc);

    cudaFuncSetAttribute(decode_kernel, cudaFuncAttributeMaxDynamicSharedMemorySize, DEC_SMEM_BYTES);
    decode_kernel<<<B, 256, DEC_SMEM_BYTES>>>(enc, capacity, demand, Tptr, out, ns, B);
}

// round 4
// speedup vs baseline: 1.0045x; 1.0045x over previous
#include <cuda_runtime.h>
#include <math.h>

#define Bmax 1024
#define Nn   100
#define Hh   128
#define NHEADS 8
#define HD   16
#define NPAD 101
#define JALL 384
#define NEGV -1000000000.0f

// ---- device scratch (no cudaMalloc allowed) ----
__device__ float g_Wcat[Hh * JALL];            // [k][j] combined Wk^T | Wv^T | Wk2^T@Wo
__device__ float g_Wqf [Hh * (Hh + 1)];        // Wq @ fc_w   (128 x 129)
__device__ float g_Wq1 [Hh * Hh];              // Wq @ fc1_w  (128 x 128)
__device__ float g_qpool[Bmax * Hh];           // (pool @ fc1_w^T) @ Wq^T
__device__ float g_EncProj[(size_t)Bmax * JALL * Nn];  // [b][j][n]

// =====================================================================
// Kernel 1: combine small weight matrices
// =====================================================================
__global__ void weights_kernel(const float* __restrict__ fc_w,
                               const float* __restrict__ fc1_w,
                               const float* __restrict__ Wq,
                               const float* __restrict__ Wk,
                               const float* __restrict__ Wv,
                               const float* __restrict__ Wo,
                               const float* __restrict__ Wk2)
{
    int bid = blockIdx.x, t = threadIdx.x;   // t = 0..127
    if (bid < 384) {
        int j = bid;
        float v;
        if (j < 128) {
            v = Wk[j * 128 + t];
        } else if (j < 256) {
            v = Wv[(j - 128) * 128 + t];
        } else {
            int jp = j - 256;
            float s = 0.f;
            for (int h = 0; h < 128; h++) s += Wk2[h * 128 + t] * Wo[h * 128 + jp];
            v = s;
        }
        g_Wcat[t * 384 + j] = v;
    } else if (bid < 512) {
        int i = bid - 384;
        for (int k = t; k < 129; k += 128) {
            float s = 0.f;
            for (int j = 0; j < 128; j++) s += Wq[i * 128 + j] * fc_w[j * 129 + k];
            g_Wqf[i * 129 + k] = s;
        }
    } else {
        int i = bid - 512;
        float s = 0.f;
        for (int j = 0; j < 128; j++) s += Wq[i * 128 + j] * fc1_w[j * 128 + t];
        g_Wq1[i * 128 + t] = s;
    }
}

// =====================================================================
// Kernel 2: qpool[b][h] = sum_k Wq1[h][k] * pool[b][k]
// =====================================================================
__global__ void qpool_kernel(const float* __restrict__ pool)
{
    int b = blockIdx.x, h = threadIdx.x;
    float s = 0.f;
    for (int k = 0; k < 128; k++) s += g_Wq1[h * 128 + k] * pool[b * 128 + k];
    g_qpool[b * 128 + h] = s;
}

// =====================================================================
// Kernel 3: EncProj[b][j][n] = sum_k enc[b][n][k] * Wcat[k][j]
// =====================================================================
__global__ __launch_bounds__(384, 1)
void encproj_kernel(const float* __restrict__ enc)
{
    extern __shared__ float As[];            // [100][128]
    int b = blockIdx.x, t = threadIdx.x;
    for (int i = t; i < Nn * Hh; i += 384) As[i] = enc[(size_t)b * Nn * Hh + i];
    float w[128];
#pragma unroll
    for (int k = 0; k < 128; k++) w[k] = g_Wcat[k * 384 + t];
    __syncthreads();

    float* op = g_EncProj + (size_t)b * JALL * Nn + (size_t)t * Nn;
    for (int n0 = 0; n0 < Nn; n0 += 4) {
        float a0 = 0.f, a1 = 0.f, a2 = 0.f, a3 = 0.f;
        const float4* r0 = reinterpret_cast<const float4*>(&As[(n0 + 0) * Hh]);
        const float4* r1 = reinterpret_cast<const float4*>(&As[(n0 + 1) * Hh]);
        const float4* r2 = reinterpret_cast<const float4*>(&As[(n0 + 2) * Hh]);
        const float4* r3 = reinterpret_cast<const float4*>(&As[(n0 + 3) * Hh]);
#pragma unroll
        for (int kk = 0; kk < 32; kk++) {
            float4 x0 = r0[kk];
            a0 += x0.x * w[4*kk] + x0.y * w[4*kk+1] + x0.z * w[4*kk+2] + x0.w * w[4*kk+3];
            float4 x1 = r1[kk];
            a1 += x1.x * w[4*kk] + x1.y * w[4*kk+1] + x1.z * w[4*kk+2] + x1.w * w[4*kk+3];
            float4 x2 = r2[kk];
            a2 += x2.x * w[4*kk] + x2.y * w[4*kk+1] + x2.z * w[4*kk+2] + x2.w * w[4*kk+3];
            float4 x3 = r3[kk];
            a3 += x3.x * w[4*kk] + x3.y * w[4*kk+1] + x3.z * w[4*kk+2] + x3.w * w[4*kk+3];
        }
        reinterpret_cast<float4*>(op + n0)[0] = make_float4(a0, a1, a2, a3);
    }
}

// =====================================================================
// Kernel 4: persistent per-batch decoder, 512 threads, active-list
// compaction, Wqf in registers.
// =====================================================================
#define DEC_SMEM_FLOATS (Hh*NPAD*3 + 128 + 132 + 128 + 800 + 128 + 104 + 104 + 104 + 8 + 120)
#define DEC_SMEM_BYTES  (DEC_SMEM_FLOATS * 4)

// rebuild active list (call from warp 0 only). act sorted ascending.
__device__ __forceinline__ void rebuild_active(int lane, int last_idx, float cap,
                                               const float* __restrict__ dem,
                                               const float* __restrict__ mask1,
                                               int* __restrict__ act, int* __restrict__ na_out)
{
    unsigned ball[4];
#pragma unroll
    for (int r = 0; r < 4; r++) {
        int n = r * 32 + lane;
        bool f = (n >= 1) && (n < Nn) && (mask1[n] == 0.f) && (dem[n] <= cap);
        ball[r] = __ballot_sync(0xffffffffu, f);
    }
    bool anyCust = (ball[0] | ball[1] | ball[2] | ball[3]) != 0u;
    bool depotA = (!anyCust) || (last_idx != 0);
    if (depotA) ball[0] |= 1u;
    int base = 0;
#pragma unroll
    for (int r = 0; r < 4; r++) {
        unsigned bl = ball[r];
        if ((bl >> lane) & 1u)
            act[base + __popc(bl & ((1u << lane) - 1u))] = r * 32 + lane;
        base += __popc(bl);
    }
    if (lane == 0) *na_out = base;
}

__global__ __launch_bounds__(512, 1)
void decode_kernel(const float* __restrict__ enc,
                   const float* __restrict__ capacity,
                   const float* __restrict__ demand,
                   const int*   __restrict__ Tptr,
                   float* __restrict__ out, int ns, int B)
{
    extern __shared__ float sm[];
    float* KT    = sm;                    // 128*101 K^T [h'][n]
    float* VT    = KT   + Hh * NPAD;      // 128*101
    float* K2T   = VT   + Hh * NPAD;      // 128*101 (K2@Wo)^T
    float* qp    = K2T  + Hh * NPAD;      // 128
    float* x     = qp   + 128;            // 132 ([inp, cap])
    float* q     = x    + 132;            // 128
    float* att   = q    + 128;            // 800
    float* g     = att  + 800;            // 128
    float* u     = g    + 128;            // 104
    float* dem   = u    + 104;            // 104
    float* mask1 = dem  + 104;            // 104
    float* misc  = mask1+ 104;            // 8: [0]=cap [1]=base [2]=logp [3]=invT
    int*   imisc = (int*)(misc + 8);      // [0]=idx [1]=visited [2]=na
    int*   act   = imisc + 8;             // 104

    const int b = blockIdx.x, t = threadIdx.x;
    const int w = t >> 5, lane = t & 31;
    const int h4 = t >> 2, p4 = t & 3;    // h4: 0..127, p4: 0..3

    // ---- load per-batch operands (transposed, pad 101) ----
    const float* ep = g_EncProj + (size_t)b * JALL * Nn;
    for (int i = t; i < JALL * Nn; i += 512) {
        int j = i / Nn, n = i - j * Nn;
        sm[(j >> 7) * (Hh * NPAD) + (j & 127) * NPAD + n] = ep[i];
    }
    // Wqf row-half in registers, bank-staggered to match x access
    float wreg[32], wex;
    {
        const float* wr = g_Wqf + h4 * 129 + p4 * 32;
#pragma unroll
        for (int rr = 0; rr < 32; rr++) wreg[rr] = wr[(rr + p4 * 8) & 31];
        wex = (p4 == 3) ? g_Wqf[h4 * 129 + 128] : 0.f;
    }
    if (t < 128) qp[t] = g_qpool[b * 128 + t];
    if (t < Nn) { dem[t] = demand[b * Nn + t]; mask1[t] = 0.f; }
    if (t < 128) x[t] = enc[(size_t)b * Nn * Hh + t];
    if (t == 0) {
        float c = capacity[b];
        misc[0] = c; misc[1] = capacity[0]; misc[2] = 0.f;
        misc[3] = 1.0f / (float)(*Tptr);
        x[128] = c;
        imisc[0] = 0; imisc[1] = 0;
    }
    __syncthreads();

    if (w == 0) rebuild_active(lane, 0, misc[0], dem, mask1, act, &imisc[2]);
    __syncthreads();

    for (int step = 0; step < ns; step++) {
        // ---- q[h] = Wqf[h]·x + qpool[h]  (4 partials/h via shfl) ----
        {
            const float* xx = x + p4 * 32;
            float s = 0.f;
#pragma unroll
            for (int rr = 0; rr < 32; rr++) s += wreg[rr] * xx[(rr + p4 * 8) & 31];
            s += wex * x[128];
            s += __shfl_xor_sync(0xffffffffu, s, 1);
            s += __shfl_xor_sync(0xffffffffu, s, 2);
            if (p4 == 0) q[h4] = qp[h4] + s;
        }
        __syncthreads();

        const int na = imisc[2];

        // ---- scores for active nodes ----
        for (int idx = t; idx < NHEADS * na; idx += 512) {
            int head = idx / na, i = idx - head * na;
            int n = act[i];
            const float* kp = KT + head * HD * NPAD + n;
            const float* qh = q + head * HD;
            float sc = 0.f;
#pragma unroll
            for (int d = 0; d < HD; d++) sc += qh[d] * kp[d * NPAD];
            att[head * Nn + i] = sc * 0.25f;
        }
        __syncthreads();

        // ---- softmax per head over na entries (warps 0..7) ----
        if (w < NHEADS) {
            float v[4], m = -3.4e38f;
#pragma unroll
            for (int r = 0; r < 4; r++) {
                int i = lane + 32 * r;
                v[r] = (i < na) ? att[w * Nn + i] : -3.4e38f;
                m = fmaxf(m, v[r]);
            }
#pragma unroll
            for (int off = 16; off; off >>= 1) m = fmaxf(m, __shfl_xor_sync(0xffffffffu, m, off));
            float e[4], ss = 0.f;
#pragma unroll
            for (int r = 0; r < 4; r++) {
                int i = lane + 32 * r;
                e[r] = (i < na) ? expf(v[r] - m) : 0.f;
                ss += e[r];
            }
#pragma unroll
            for (int off = 16; off; off >>= 1) ss += __shfl_xor_sync(0xffffffffu, ss, off);
            float inv = 1.f / ss;
#pragma unroll
            for (int r = 0; r < 4; r++) {
                int i = lane + 32 * r;
                if (i < na) att[w * Nn + i] = e[r] * inv;
            }
        }
        __syncthreads();

        // ---- g[h] = attn · V over active (4 partials/h via shfl) ----
        {
            const float* vp = VT + h4 * NPAD;
            const float* ap = att + (h4 >> 4) * Nn;
            float sg = 0.f;
            for (int i = p4; i < na; i += 4) sg += ap[i] * vp[act[i]];
            sg += __shfl_xor_sync(0xffffffffu, sg, 1);
            sg += __shfl_xor_sync(0xffffffffu, sg, 2);
            if (p4 == 0) g[h4] = sg;
        }
        __syncthreads();

        // ---- u[i] = CLIP*tanh(g · K2T[:,act[i]] / sqrt(H)) ----
        // NOTE: every thread executes the shuffles (full-mask); inactive
        // threads compute against column 0 and discard. Guarding the body
        // with (h4 < na) deadlocks warps straddling the na boundary.
        {
            const bool vi = (h4 < na);
            const float* kp = K2T + (vi ? act[h4] : 0);
            float su = 0.f;
#pragma unroll
            for (int rr = 0; rr < 32; rr++) {
                int j = p4 * 32 + ((rr + p4 * 8) & 31);
                su += g[j] * kp[j * NPAD];
            }
            su += __shfl_xor_sync(0xffffffffu, su, 1);
            su += __shfl_xor_sync(0xffffffffu, su, 2);
            if (p4 == 0 && vi) u[h4] = 10.f * tanhf(su * 0.08838834764831845f);
        }
        __syncthreads();

        // ---- argmax + log-softmax + state update + rebuild (warp 0) ----
        if (w == 0) {
            float invT = misc[3];
            float best = -3.4e38f; int bn = 0x7fffffff;
            float v[4];
#pragma unroll
            for (int r = 0; r < 4; r++) {
                int i = lane + 32 * r;
                if (i < na) {
                    float val = u[i] * invT;
                    int n = act[i]; v[r] = val;
                    if (val > best) { best = val; bn = n; }
                } else { v[r] = -3.4e38f; }
            }
#pragma unroll
            for (int off = 16; off; off >>= 1) {
                float ov = __shfl_xor_sync(0xffffffffu, best, off);
                int   on = __shfl_xor_sync(0xffffffffu, bn,   off);
                if (ov > best || (ov == best && on < bn)) { best = ov; bn = on; }
            }
            float ss = 0.f;
#pragma unroll
            for (int r = 0; r < 4; r++) {
                int i = lane + 32 * r;
                ss += (i < na) ? expf(v[r] - best) : 0.f;
            }
#pragma unroll
            for (int off = 16; off; off >>= 1) ss += __shfl_xor_sync(0xffffffffu, ss, off);

            if (lane == 0) {
                int idx = bn;
                imisc[0] = idx;
                if (imisc[1] < Nn - 1) misc[2] += -logf(ss);
                out[(size_t)b * ns + step] = (float)idx;
                float c = (idx == 0) ? misc[1] : misc[0] - dem[idx];
                misc[0] = c;
                x[128] = c;
                if (idx > 0 && mask1[idx] == 0.f) { mask1[idx] = 1.f; imisc[1] += 1; }
            }
            __syncwarp();
            rebuild_active(lane, imisc[0], misc[0], dem, mask1, act, &imisc[2]);
        }
        __syncthreads();

        // ---- gather next input row ----
        int sidx = imisc[0];
        if (t < 128) x[t] = enc[(size_t)b * Nn * Hh + (size_t)sidx * Hh + t];
        __syncthreads();
    }

    if (t == 0) out[(size_t)B * ns + b] = misc[2];
}

// =====================================================================
// launch
// =====================================================================
extern "C" void kernel_launch(void* const* d_in, const int* in_sizes, int n_in,
                              void* d_out, int out_size)
{
    const float* enc      = (const float*)d_in[0];
    const float* pool     = (const float*)d_in[1];
    const float* capacity = (const float*)d_in[2];
    const float* demand   = (const float*)d_in[3];
    const float* fc_w     = (const float*)d_in[4];
    const float* fc1_w    = (const float*)d_in[5];
    const float* Wq       = (const float*)d_in[6];
    const float* Wk       = (const float*)d_in[7];
    const float* Wv       = (const float*)d_in[8];
    const float* Wo       = (const float*)d_in[9];
    const float* Wk2      = (const float*)d_in[10];
    const int*   Tptr     = (const int*)d_in[12];

    int B  = in_sizes[0] / (Nn * Hh);          // 1024
    int ns = out_size / B - 1;                 // 128
    float* out = (float*)d_out;

    weights_kernel<<<640, 128>>>(fc_w, fc1_w, Wq, Wk, Wv, Wo, Wk2);
    qpool_kernel<<<B, 128>>>(pool);

    cudaFuncSetAttribute(encproj_kernel, cudaFuncAttributeMaxDynamicSharedMemorySize, Nn * Hh * 4);
    encproj_kernel<<<B, 384, Nn * Hh * 4>>>(enc);

    cudaFuncSetAttribute(decode_kernel, cudaFuncAttributeMaxDynamicSharedMemorySize, DEC_SMEM_BYTES);
    decode_kernel<<<B, 512, DEC_SMEM_BYTES>>>(enc, capacity, demand, Tptr, out, ns, B);
}